// round 5
// baseline (speedup 1.0000x reference)
#include <cuda_runtime.h>
#include <cuda_bf16.h>

#define NN 100000
#define FF 64
#define HH 128
#define CC 10
#define EE 1600000

typedef unsigned int uint;

// ---------------- scratch ----------------
__device__ uint g_P0h[(size_t)NN * 64], g_P0l[(size_t)NN * 64];   // pair buffers (packed bf16x2)
__device__ uint g_P1h[(size_t)NN * 64], g_P1l[(size_t)NN * 64];
__device__ uint g_P2h[(size_t)NN * 64], g_P2l[(size_t)NN * 64];
__device__ float g_h[(size_t)NN * HH];
__device__ uint g_Wh[5 * 8192], g_Wl[5 * 8192];
__device__ int g_deg[NN], g_rowptr[NN + 1], g_cur[NN], g_adj[EE];
__device__ float g_stats[512];
__device__ int g_is64;

// ---------------- helpers ----------------
__device__ __forceinline__ uint pckbf(__nv_bfloat16 a, __nv_bfloat16 b) {
    __nv_bfloat162 t; t.x = a; t.y = b;
    return *reinterpret_cast<uint*>(&t);
}
__device__ __forceinline__ void split2(float x, float y, uint& h, uint& l) {
    __nv_bfloat16 hx = __float2bfloat16_rn(x), hy = __float2bfloat16_rn(y);
    float rx = x - __bfloat162float(hx), ry = y - __bfloat162float(hy);
    h = pckbf(hx, hy);
    l = pckbf(__float2bfloat16_rn(rx), __float2bfloat16_rn(ry));
}
__device__ __forceinline__ float2 bf2f(uint u) {
    __nv_bfloat162 b = *reinterpret_cast<__nv_bfloat162*>(&u);
    return make_float2(__bfloat162float(b.x), __bfloat162float(b.y));
}
__device__ __forceinline__ void mma16816(float* d, uint a0, uint a1, uint a2,
                                         uint a3, uint b0, uint b1) {
    asm volatile("mma.sync.aligned.m16n8k16.row.col.f32.bf16.bf16.f32 "
                 "{%0,%1,%2,%3},{%4,%5,%6,%7},{%8,%9},{%0,%1,%2,%3};"
                 : "+f"(d[0]), "+f"(d[1]), "+f"(d[2]), "+f"(d[3])
                 : "r"(a0), "r"(a1), "r"(a2), "r"(a3), "r"(b0), "r"(b1));
}
__device__ __forceinline__ void eidx(const int* ei, int e, int& s, int& d) {
    if (g_is64) { s = ei[2 * e]; d = ei[2 * EE + 2 * e]; }
    else        { s = ei[e];     d = ei[EE + e]; }
}

// ---------------- CSR build ----------------
__global__ void k_detect(const int* __restrict__ ei) {
    if (threadIdx.x == 0) {
        int nz = 0;
        for (int i = 0; i < 1024; i++) nz |= ei[2 * i + 1];
        g_is64 = (nz == 0) ? 1 : 0;
    }
}
__global__ void k_zero_deg() {
    int i = blockIdx.x * blockDim.x + threadIdx.x;
    if (i < NN) g_deg[i] = 0;
}
__global__ void k_deg(const int* __restrict__ ei) {
    int e = blockIdx.x * blockDim.x + threadIdx.x;
    if (e >= EE) return;
    int s, d;
    eidx(ei, e, s, d);
    if ((unsigned)s >= NN || (unsigned)d >= NN) return;
    atomicAdd(&g_deg[d], 1);
}
__global__ void k_scan() {
    __shared__ int part[1024];
    const int CHUNK = (NN + 1023) / 1024;
    int t = threadIdx.x;
    int base = t * CHUNK, lim = min(base + CHUNK, NN);
    int s = 0;
    for (int i = base; i < lim; i++) s += g_deg[i];
    part[t] = s;
    __syncthreads();
    for (int off = 1; off < 1024; off <<= 1) {
        int v = (t >= off) ? part[t - off] : 0;
        __syncthreads();
        part[t] += v;
        __syncthreads();
    }
    int run = (t == 0) ? 0 : part[t - 1];
    for (int i = base; i < lim; i++) {
        g_rowptr[i] = run;
        g_cur[i] = run;
        run += g_deg[i];
    }
    if (t == 1023) g_rowptr[NN] = part[1023];
}
__global__ void k_fill(const int* __restrict__ ei) {
    int e = blockIdx.x * blockDim.x + threadIdx.x;
    if (e >= EE) return;
    int s, d;
    eidx(ei, e, s, d);
    if ((unsigned)s >= NN || (unsigned)d >= NN) return;
    int pos = atomicAdd(&g_cur[d], 1);
    g_adj[pos] = s;
}

// ---------------- weight pre-split: W[K][128] fp32 -> [n][K/2] packed pairs ----------------
__global__ void k_wsplit(const float* __restrict__ W, uint* __restrict__ Wh,
                         uint* __restrict__ Wl, int K) {
    int RW = K / 2;
    int i = blockIdx.x * blockDim.x + threadIdx.x;
    if (i >= 128 * RW) return;
    int n = i / RW, kp = i - n * RW;
    float a = W[(size_t)(2 * kp) * 128 + n];
    float b = W[(size_t)(2 * kp + 1) * 128 + n];
    split2(a, b, Wh[i], Wl[i]);
}

// ---------------- gather1: agg = x_self + sum x_j, split to pair (width 64) ----------------
__global__ void k_gather1(const float* __restrict__ x, uint* __restrict__ Oh,
                          uint* __restrict__ Ol) {
    int gi = blockIdx.x * blockDim.x + threadIdx.x;
    int node = gi >> 4, l = gi & 15;
    if (node >= NN) return;
    const float4* xr = (const float4*)x;
    size_t co = (size_t)node * 16 + l;
    float4 acc = xr[co];
    int p = g_rowptr[node], end = g_rowptr[node + 1];
    for (; p + 1 < end; p += 2) {
        int j0 = g_adj[p], j1 = g_adj[p + 1];
        float4 a = xr[(size_t)j0 * 16 + l];
        float4 b = xr[(size_t)j1 * 16 + l];
        acc.x += a.x + b.x; acc.y += a.y + b.y;
        acc.z += a.z + b.z; acc.w += a.w + b.w;
    }
    if (p < end) {
        float4 a = xr[(size_t)g_adj[p] * 16 + l];
        acc.x += a.x; acc.y += a.y; acc.z += a.z; acc.w += a.w;
    }
    uint h0, l0, h1, l1;
    split2(acc.x, acc.y, h0, l0);
    split2(acc.z, acc.w, h1, l1);
    size_t o = (size_t)node * 32 + l * 2;
    *(uint2*)(Oh + o) = make_uint2(h0, h1);
    *(uint2*)(Ol + o) = make_uint2(l0, l1);
}

// ---------------- gather2: agg = sum_{self+nbrs} relu(bn(v)), pair width 128 ----------------
__global__ void k_gather2(const uint* __restrict__ Ih, const uint* __restrict__ Il,
                          uint* __restrict__ Oh, uint* __restrict__ Ol) {
    int node = blockIdx.x * 4 + (threadIdx.x >> 5);
    int l = threadIdx.x & 31;
    if (node >= NN) return;
    float4 sc = *(const float4*)&g_stats[256 + l * 4];
    float4 sh = *(const float4*)&g_stats[384 + l * 4];
    float a0 = 0.f, a1 = 0.f, a2 = 0.f, a3 = 0.f;
#define ADDROW(j) do { \
        size_t _o = (size_t)(j) * 64 + l * 2; \
        uint2 uh = *(const uint2*)(Ih + _o); \
        uint2 ul = *(const uint2*)(Il + _o); \
        float2 fa = bf2f(uh.x), fb = bf2f(ul.x), fc = bf2f(uh.y), fd = bf2f(ul.y); \
        a0 += fmaxf(fmaf(fa.x + fb.x, sc.x, sh.x), 0.f); \
        a1 += fmaxf(fmaf(fa.y + fb.y, sc.y, sh.y), 0.f); \
        a2 += fmaxf(fmaf(fc.x + fd.x, sc.z, sh.z), 0.f); \
        a3 += fmaxf(fmaf(fc.y + fd.y, sc.w, sh.w), 0.f); \
    } while (0)
    ADDROW(node);
    int p = g_rowptr[node], end = g_rowptr[node + 1];
    for (; p + 1 < end; p += 2) {
        int j0 = g_adj[p], j1 = g_adj[p + 1];
        ADDROW(j0);
        ADDROW(j1);
    }
    if (p < end) ADDROW(g_adj[p]);
#undef ADDROW
    uint h0, l0, h1, l1;
    split2(a0, a1, h0, l0);
    split2(a2, a3, h1, l1);
    size_t o = (size_t)node * 64 + l * 2;
    *(uint2*)(Oh + o) = make_uint2(h0, h1);
    *(uint2*)(Ol + o) = make_uint2(l0, l1);
}

// ---------------- mma.sync bf16-split3 GEMM (pair inputs): Out = act(A@W + b) ----------------
// 256 threads, 128x128 tile, 8 warps (4m x 2n), warp tile 32x64, k-chunk 16.
template <int K, bool RELU, bool PAIROUT>
__global__ void __launch_bounds__(256, 2)
k_mgemm(const uint* __restrict__ Ah, const uint* __restrict__ Al,
        const uint* __restrict__ Wh, const uint* __restrict__ Wl,
        const float* __restrict__ bias,
        float* __restrict__ OutF, uint* __restrict__ Oh, uint* __restrict__ Ol) {
    __shared__ uint Ash[128][9], Asl[128][9];
    __shared__ uint Bsh[128][9], Bsl[128][9];
    __shared__ float sbias[128];

    const int tid = threadIdx.x;
    const int wid = tid >> 5, lane = tid & 31;
    const int wm = wid >> 1, wn = wid & 1;
    const int g = lane >> 2, t = lane & 3;
    const int row0 = blockIdx.x * 128;
    const int RW = K / 2;

    if (tid < 128) sbias[tid] = bias[tid];

    float acc[2][8][4];
    #pragma unroll
    for (int i = 0; i < 2; i++)
        #pragma unroll
        for (int j = 0; j < 8; j++)
            #pragma unroll
            for (int q = 0; q < 4; q++) acc[i][j][q] = 0.f;

    const int CHK = K / 16;
    for (int c = 0; c < CHK; c++) {
        __syncthreads();
        {   // stage A: pure copies (data already split+packed)
            int r = tid >> 1, half = tid & 1;
            uint4 vh = make_uint4(0, 0, 0, 0), vl = vh;
            if (row0 + r < NN) {
                size_t o = (size_t)(row0 + r) * RW + c * 8 + half * 4;
                vh = *(const uint4*)(Ah + o);
                vl = *(const uint4*)(Al + o);
            }
            int b = half * 4;
            Ash[r][b] = vh.x; Ash[r][b + 1] = vh.y; Ash[r][b + 2] = vh.z; Ash[r][b + 3] = vh.w;
            Asl[r][b] = vl.x; Asl[r][b + 1] = vl.y; Asl[r][b + 2] = vl.z; Asl[r][b + 3] = vl.w;
        }
        {   // stage B: pre-transposed pre-split weights
            int n = tid >> 1, half = tid & 1;
            size_t o = (size_t)n * RW + c * 8 + half * 4;
            uint4 wh = *(const uint4*)(Wh + o);
            uint4 wl = *(const uint4*)(Wl + o);
            int b = half * 4;
            Bsh[n][b] = wh.x; Bsh[n][b + 1] = wh.y; Bsh[n][b + 2] = wh.z; Bsh[n][b + 3] = wh.w;
            Bsl[n][b] = wl.x; Bsl[n][b + 1] = wl.y; Bsl[n][b + 2] = wl.z; Bsl[n][b + 3] = wl.w;
        }
        __syncthreads();
        uint bh[8][2], bl[8][2];
        #pragma unroll
        for (int nt = 0; nt < 8; nt++) {
            int n = wn * 64 + nt * 8 + g;
            bh[nt][0] = Bsh[n][t]; bh[nt][1] = Bsh[n][t + 4];
            bl[nt][0] = Bsl[n][t]; bl[nt][1] = Bsl[n][t + 4];
        }
        #pragma unroll
        for (int mt = 0; mt < 2; mt++) {
            int rb = wm * 32 + mt * 16;
            uint ah0 = Ash[rb + g][t],     ah1 = Ash[rb + 8 + g][t];
            uint ah2 = Ash[rb + g][t + 4], ah3 = Ash[rb + 8 + g][t + 4];
            uint al0 = Asl[rb + g][t],     al1 = Asl[rb + 8 + g][t];
            uint al2 = Asl[rb + g][t + 4], al3 = Asl[rb + 8 + g][t + 4];
            #pragma unroll
            for (int nt = 0; nt < 8; nt++) {
                mma16816(acc[mt][nt], ah0, ah1, ah2, ah3, bh[nt][0], bh[nt][1]);
                mma16816(acc[mt][nt], ah0, ah1, ah2, ah3, bl[nt][0], bl[nt][1]);
                mma16816(acc[mt][nt], al0, al1, al2, al3, bh[nt][0], bh[nt][1]);
            }
        }
    }
    // epilogue
    #pragma unroll
    for (int mt = 0; mt < 2; mt++) {
        #pragma unroll
        for (int nt = 0; nt < 8; nt++) {
            int cc = wn * 64 + nt * 8 + 2 * t;
            float b0 = sbias[cc], b1 = sbias[cc + 1];
            int r0r = row0 + wm * 32 + mt * 16 + g;
            float d0 = acc[mt][nt][0] + b0, d1 = acc[mt][nt][1] + b1;
            float d2 = acc[mt][nt][2] + b0, d3 = acc[mt][nt][3] + b1;
            if (RELU) {
                d0 = fmaxf(d0, 0.f); d1 = fmaxf(d1, 0.f);
                d2 = fmaxf(d2, 0.f); d3 = fmaxf(d3, 0.f);
            }
            if (PAIROUT) {
                uint h, l;
                if (r0r < NN) {
                    split2(d0, d1, h, l);
                    Oh[(size_t)r0r * 64 + (cc >> 1)] = h;
                    Ol[(size_t)r0r * 64 + (cc >> 1)] = l;
                }
                if (r0r + 8 < NN) {
                    split2(d2, d3, h, l);
                    Oh[(size_t)(r0r + 8) * 64 + (cc >> 1)] = h;
                    Ol[(size_t)(r0r + 8) * 64 + (cc >> 1)] = l;
                }
            } else {
                if (r0r < NN) *(float2*)(OutF + (size_t)r0r * 128 + cc) = make_float2(d0, d1);
                if (r0r + 8 < NN) *(float2*)(OutF + (size_t)(r0r + 8) * 128 + cc) = make_float2(d2, d3);
            }
        }
    }
}

// ---------------- BatchNorm ----------------
__global__ void k_zero_stats() { g_stats[threadIdx.x] = 0.f; }

__global__ void k_stats_pair(const uint* __restrict__ Ih, const uint* __restrict__ Il) {
    int c = threadIdx.x;          // 0..127
    int half = c & 1;
    float s = 0.f, q = 0.f;
    for (int r = blockIdx.x; r < NN; r += gridDim.x) {
        size_t o = (size_t)r * 64 + (c >> 1);
        float2 fh = bf2f(Ih[o]);
        float2 fl = bf2f(Il[o]);
        float v = half ? (fh.y + fl.y) : (fh.x + fl.x);
        s += v;
        q = fmaf(v, v, q);
    }
    atomicAdd(&g_stats[c], s);
    atomicAdd(&g_stats[128 + c], q);
}

__global__ void k_bnfin(const float* __restrict__ g, const float* __restrict__ b) {
    int c = threadIdx.x;
    float inv = 1.f / (float)NN;
    float mean = g_stats[c] * inv;
    float var = g_stats[128 + c] * inv - mean * mean;
    float rstd = rsqrtf(var + 1e-5f);
    float sc = g[c] * rstd;
    g_stats[256 + c] = sc;
    g_stats[384 + c] = b[c] - mean * sc;
}

// bnapply2: pair in -> fp32 latent (d_out) + pair out (classifier input)
__global__ void k_bnapply2(const uint* __restrict__ Ih, const uint* __restrict__ Il,
                           float* __restrict__ OutF, uint* __restrict__ Oh,
                           uint* __restrict__ Ol) {
    int i = blockIdx.x * blockDim.x + threadIdx.x;
    if (i >= NN * 64) return;
    int pc = i & 63;
    int c = pc * 2;
    float2 fh = bf2f(Ih[i]);
    float2 fl = bf2f(Il[i]);
    float v0 = fh.x + fl.x, v1 = fh.y + fl.y;
    float y0 = fmaxf(fmaf(v0, g_stats[256 + c], g_stats[384 + c]), 0.f);
    float y1 = fmaxf(fmaf(v1, g_stats[257 + c], g_stats[385 + c]), 0.f);
    int r = i >> 6;
    *(float2*)(OutF + (size_t)r * 128 + c) = make_float2(y0, y1);
    uint h, l;
    split2(y0, y1, h, l);
    Oh[i] = h;
    Ol[i] = l;
}

// ---------------- classifier head: out[N,10] = m[N,128] @ w[128,10] + b ----------------
__global__ void __launch_bounds__(128) k_out(const float* __restrict__ m,
                                             const float* __restrict__ w,
                                             const float* __restrict__ b,
                                             float* __restrict__ out) {
    __shared__ float Wsm[1280];
    __shared__ float Ms[128][33];
    int tid = threadIdx.x;
    for (int i = tid; i < 1280; i += 128) Wsm[i] = w[i];
    long long row0 = (long long)blockIdx.x * 128;
    float acc[10];
    #pragma unroll
    for (int c = 0; c < 10; c++) acc[c] = b[c];
    for (int k0 = 0; k0 < 128; k0 += 32) {
        __syncthreads();
        for (int i = tid; i < 1024; i += 128) {
            int r = i >> 3, c4 = i & 7;
            long long gr = row0 + r;
            float4 v = make_float4(0.f, 0.f, 0.f, 0.f);
            if (gr < NN) v = *(const float4*)(m + gr * 128 + k0 + c4 * 4);
            Ms[r][c4 * 4] = v.x; Ms[r][c4 * 4 + 1] = v.y;
            Ms[r][c4 * 4 + 2] = v.z; Ms[r][c4 * 4 + 3] = v.w;
        }
        __syncthreads();
        #pragma unroll
        for (int kk = 0; kk < 32; kk++) {
            float a = Ms[tid][kk];
            #pragma unroll
            for (int c = 0; c < 10; c++) acc[c] = fmaf(a, Wsm[(k0 + kk) * 10 + c], acc[c]);
        }
    }
    long long gr = row0 + tid;
    if (gr < NN) {
        #pragma unroll
        for (int c = 0; c < 10; c++) out[gr * 10 + c] = acc[c];
    }
}

// ---------------- launch ----------------
extern "C" void kernel_launch(void* const* d_in, const int* in_sizes, int n_in,
                              void* d_out, int out_size) {
    const float* x    = (const float*)d_in[0];
    const int*   ei   = (const int*)d_in[1];
    const float* w1a = (const float*)d_in[2];  const float* b1a = (const float*)d_in[3];
    const float* w1b = (const float*)d_in[4];  const float* b1b = (const float*)d_in[5];
    const float* w2a = (const float*)d_in[6];  const float* b2a = (const float*)d_in[7];
    const float* w2b = (const float*)d_in[8];  const float* b2b = (const float*)d_in[9];
    const float* bn1g = (const float*)d_in[10]; const float* bn1b = (const float*)d_in[11];
    const float* bn2g = (const float*)d_in[12]; const float* bn2b = (const float*)d_in[13];
    const float* mw1 = (const float*)d_in[14]; const float* mb1 = (const float*)d_in[15];
    const float* mw2 = (const float*)d_in[16]; const float* mb2 = (const float*)d_in[17];
    float* out = (float*)d_out;

    uint *P0h, *P0l, *P1h, *P1l, *P2h, *P2l, *Wh, *Wl;
    float* hh;
    cudaGetSymbolAddress((void**)&P0h, g_P0h); cudaGetSymbolAddress((void**)&P0l, g_P0l);
    cudaGetSymbolAddress((void**)&P1h, g_P1h); cudaGetSymbolAddress((void**)&P1l, g_P1l);
    cudaGetSymbolAddress((void**)&P2h, g_P2h); cudaGetSymbolAddress((void**)&P2l, g_P2l);
    cudaGetSymbolAddress((void**)&Wh, g_Wh);   cudaGetSymbolAddress((void**)&Wl, g_Wl);
    cudaGetSymbolAddress((void**)&hh, g_h);

    const int GB = (NN + 127) / 128;  // 782
    const int EB = (EE + 255) / 256;

    // ---- CSR build (once; reused by both convs)
    k_detect<<<1, 32>>>(ei);
    k_zero_deg<<<(NN + 255) / 256, 256>>>();
    k_deg<<<EB, 256>>>(ei);
    k_scan<<<1, 1024>>>();
    k_fill<<<EB, 256>>>(ei);

    // ---- weight pre-split (slot stride 8192)
    k_wsplit<<<(128 * 32 + 255) / 256, 256>>>(w1a, Wh + 0 * 8192, Wl + 0 * 8192, 64);
    k_wsplit<<<(128 * 64 + 255) / 256, 256>>>(w1b, Wh + 1 * 8192, Wl + 1 * 8192, 128);
    k_wsplit<<<(128 * 64 + 255) / 256, 256>>>(w2a, Wh + 2 * 8192, Wl + 2 * 8192, 128);
    k_wsplit<<<(128 * 64 + 255) / 256, 256>>>(w2b, Wh + 3 * 8192, Wl + 3 * 8192, 128);
    k_wsplit<<<(128 * 64 + 255) / 256, 256>>>(mw1, Wh + 4 * 8192, Wl + 4 * 8192, 128);

    // ---- conv1
    k_gather1<<<(NN * 16 + 127) / 128, 128>>>(x, P0h, P0l);
    k_mgemm<64, true, true><<<GB, 256>>>(P0h, P0l, Wh, Wl, b1a, 0, P1h, P1l);
    k_mgemm<128, false, true><<<GB, 256>>>(P1h, P1l, Wh + 8192, Wl + 8192, b1b, 0, P2h, P2l);
    // ---- bn1 stats (apply fused into gather2)
    k_zero_stats<<<1, 512>>>();
    k_stats_pair<<<512, 128>>>(P2h, P2l);
    k_bnfin<<<1, 128>>>(bn1g, bn1b);
    // ---- conv2 (gather applies relu(bn(.)) per term)
    k_gather2<<<(NN + 3) / 4, 128>>>(P2h, P2l, P0h, P0l);
    k_mgemm<128, true, true><<<GB, 256>>>(P0h, P0l, Wh + 2 * 8192, Wl + 2 * 8192, b2a, 0, P1h, P1l);
    k_mgemm<128, false, true><<<GB, 256>>>(P1h, P1l, Wh + 3 * 8192, Wl + 3 * 8192, b2b, 0, P2h, P2l);
    // ---- bn2 -> latent fp32 (d_out) + pair for classifier
    k_zero_stats<<<1, 512>>>();
    k_stats_pair<<<512, 128>>>(P2h, P2l);
    k_bnfin<<<1, 128>>>(bn2g, bn2b);
    k_bnapply2<<<(NN * 64 + 255) / 256, 256>>>(P2h, P2l, out, P0h, P0l);
    // ---- classifier
    k_mgemm<128, true, false><<<GB, 256>>>(P0h, P0l, Wh + 4 * 8192, Wl + 4 * 8192, mb1, hh, 0, 0);
    k_out<<<GB, 128>>>(hh, mw2, mb2, out + (size_t)NN * 128);
}

// round 6
// speedup vs baseline: 1.1981x; 1.1981x over previous
#include <cuda_runtime.h>
#include <cuda_bf16.h>

#define NN 100000
#define FF 64
#define HH 128
#define CC 10
#define EE 1600000
#define NB 98   // ceil(NN/1024)

typedef unsigned int uint;

// ---------------- scratch ----------------
__device__ uint g_P0h[(size_t)NN * 64], g_P0l[(size_t)NN * 64];   // pair buffers (packed bf16x2)
__device__ uint g_P1h[(size_t)NN * 64], g_P1l[(size_t)NN * 64];
__device__ uint g_P2h[(size_t)NN * 64], g_P2l[(size_t)NN * 64];
__device__ float g_h[(size_t)NN * HH];
__device__ uint g_Wh[5 * 8192], g_Wl[5 * 8192];
__device__ int g_deg[NN], g_rowptr[NN + 1], g_cur[NN], g_adj[EE];
__device__ int g_bsum[NB], g_bpre[NB];
__device__ float g_stats[512];
__device__ int g_is64;

// ---------------- helpers ----------------
__device__ __forceinline__ uint pckbf(__nv_bfloat16 a, __nv_bfloat16 b) {
    __nv_bfloat162 t; t.x = a; t.y = b;
    return *reinterpret_cast<uint*>(&t);
}
__device__ __forceinline__ void split2(float x, float y, uint& h, uint& l) {
    __nv_bfloat16 hx = __float2bfloat16_rn(x), hy = __float2bfloat16_rn(y);
    float rx = x - __bfloat162float(hx), ry = y - __bfloat162float(hy);
    h = pckbf(hx, hy);
    l = pckbf(__float2bfloat16_rn(rx), __float2bfloat16_rn(ry));
}
__device__ __forceinline__ float2 bf2f(uint u) {
    __nv_bfloat162 b = *reinterpret_cast<__nv_bfloat162*>(&u);
    return make_float2(__bfloat162float(b.x), __bfloat162float(b.y));
}
__device__ __forceinline__ void mma16816(float* d, uint a0, uint a1, uint a2,
                                         uint a3, uint b0, uint b1) {
    asm volatile("mma.sync.aligned.m16n8k16.row.col.f32.bf16.bf16.f32 "
                 "{%0,%1,%2,%3},{%4,%5,%6,%7},{%8,%9},{%0,%1,%2,%3};"
                 : "+f"(d[0]), "+f"(d[1]), "+f"(d[2]), "+f"(d[3])
                 : "r"(a0), "r"(a1), "r"(a2), "r"(a3), "r"(b0), "r"(b1));
}
__device__ __forceinline__ void eidx(const int* ei, int e, int& s, int& d) {
    if (g_is64) { s = ei[2 * e]; d = ei[2 * EE + 2 * e]; }
    else        { s = ei[e];     d = ei[EE + e]; }
}

// ---------------- CSR build ----------------
__global__ void k_detect(const int* __restrict__ ei) {
    if (threadIdx.x == 0) {
        int nz = 0;
        for (int i = 0; i < 1024; i++) nz |= ei[2 * i + 1];
        g_is64 = (nz == 0) ? 1 : 0;
    }
}
__global__ void k_zero_deg() {
    int i = blockIdx.x * blockDim.x + threadIdx.x;
    if (i < NN) g_deg[i] = 0;
}
__global__ void k_deg(const int* __restrict__ ei) {
    int e = blockIdx.x * blockDim.x + threadIdx.x;
    if (e >= EE) return;
    int s, d;
    eidx(ei, e, s, d);
    if ((unsigned)s >= NN || (unsigned)d >= NN) return;
    atomicAdd(&g_deg[d], 1);
}
// phase 1: per-chunk (1024 nodes) degree sum
__global__ void k_bsum() {
    __shared__ int sh[1024];
    int t = threadIdx.x;
    int i = blockIdx.x * 1024 + t;
    sh[t] = (i < NN) ? g_deg[i] : 0;
    __syncthreads();
    for (int off = 512; off > 0; off >>= 1) {
        if (t < off) sh[t] += sh[t + off];
        __syncthreads();
    }
    if (t == 0) g_bsum[blockIdx.x] = sh[0];
}
// phase 2: exclusive scan of NB chunk sums (single block, shared Hillis-Steele)
__global__ void k_bscan() {
    __shared__ int sh[128];
    int t = threadIdx.x;
    sh[t] = (t < NB) ? g_bsum[t] : 0;
    __syncthreads();
    for (int off = 1; off < 128; off <<= 1) {
        int v = (t >= off) ? sh[t - off] : 0;
        __syncthreads();
        sh[t] += v;
        __syncthreads();
    }
    if (t < NB) g_bpre[t] = (t == 0) ? 0 : sh[t - 1];
    if (t == NB - 1) g_rowptr[NN] = sh[t];
}
// phase 3: per-chunk inclusive scan + chunk base -> rowptr/cur
__global__ void k_scan3() {
    __shared__ int sh[1024];
    int t = threadIdx.x;
    int i = blockIdx.x * 1024 + t;
    int d = (i < NN) ? g_deg[i] : 0;
    sh[t] = d;
    __syncthreads();
    for (int off = 1; off < 1024; off <<= 1) {
        int v = (t >= off) ? sh[t - off] : 0;
        __syncthreads();
        sh[t] += v;
        __syncthreads();
    }
    if (i < NN) {
        int r = g_bpre[blockIdx.x] + sh[t] - d;  // exclusive
        g_rowptr[i] = r;
        g_cur[i] = r;
    }
}
__global__ void k_fill(const int* __restrict__ ei) {
    int e = blockIdx.x * blockDim.x + threadIdx.x;
    if (e >= EE) return;
    int s, d;
    eidx(ei, e, s, d);
    if ((unsigned)s >= NN || (unsigned)d >= NN) return;
    int pos = atomicAdd(&g_cur[d], 1);
    g_adj[pos] = s;
}

// ---------------- weight pre-split: W[K][128] fp32 -> [n][K/2] packed pairs ----------------
__global__ void k_wsplit(const float* __restrict__ W, uint* __restrict__ Wh,
                         uint* __restrict__ Wl, int K) {
    int RW = K / 2;
    int i = blockIdx.x * blockDim.x + threadIdx.x;
    if (i >= 128 * RW) return;
    int n = i / RW, kp = i - n * RW;
    float a = W[(size_t)(2 * kp) * 128 + n];
    float b = W[(size_t)(2 * kp + 1) * 128 + n];
    split2(a, b, Wh[i], Wl[i]);
}

// ---------------- gather1: agg = x_self + sum x_j, split to pair (width 64) ----------------
__global__ void k_gather1(const float* __restrict__ x, uint* __restrict__ Oh,
                          uint* __restrict__ Ol) {
    int gi = blockIdx.x * blockDim.x + threadIdx.x;
    int node = gi >> 4, l = gi & 15;
    if (node >= NN) return;
    const float4* xr = (const float4*)x;
    size_t co = (size_t)node * 16 + l;
    float4 acc = xr[co];
    int p = g_rowptr[node], end = g_rowptr[node + 1];
    for (; p + 1 < end; p += 2) {
        int j0 = g_adj[p], j1 = g_adj[p + 1];
        float4 a = xr[(size_t)j0 * 16 + l];
        float4 b = xr[(size_t)j1 * 16 + l];
        acc.x += a.x + b.x; acc.y += a.y + b.y;
        acc.z += a.z + b.z; acc.w += a.w + b.w;
    }
    if (p < end) {
        float4 a = xr[(size_t)g_adj[p] * 16 + l];
        acc.x += a.x; acc.y += a.y; acc.z += a.z; acc.w += a.w;
    }
    uint h0, l0, h1, l1;
    split2(acc.x, acc.y, h0, l0);
    split2(acc.z, acc.w, h1, l1);
    size_t o = (size_t)node * 32 + l * 2;
    *(uint2*)(Oh + o) = make_uint2(h0, h1);
    *(uint2*)(Ol + o) = make_uint2(l0, l1);
}

// ---------------- gather2: agg = sum_{self+nbrs} relu(bn(v)), pair width 128 ----------------
__global__ void k_gather2(const uint* __restrict__ Ih, const uint* __restrict__ Il,
                          uint* __restrict__ Oh, uint* __restrict__ Ol) {
    int node = blockIdx.x * 4 + (threadIdx.x >> 5);
    int l = threadIdx.x & 31;
    if (node >= NN) return;
    float4 sc = *(const float4*)&g_stats[256 + l * 4];
    float4 sh = *(const float4*)&g_stats[384 + l * 4];
    float a0 = 0.f, a1 = 0.f, a2 = 0.f, a3 = 0.f;
#define ADDROW(j) do { \
        size_t _o = (size_t)(j) * 64 + l * 2; \
        uint2 uh = *(const uint2*)(Ih + _o); \
        uint2 ul = *(const uint2*)(Il + _o); \
        float2 fa = bf2f(uh.x), fb = bf2f(ul.x), fc = bf2f(uh.y), fd = bf2f(ul.y); \
        a0 += fmaxf(fmaf(fa.x + fb.x, sc.x, sh.x), 0.f); \
        a1 += fmaxf(fmaf(fa.y + fb.y, sc.y, sh.y), 0.f); \
        a2 += fmaxf(fmaf(fc.x + fd.x, sc.z, sh.z), 0.f); \
        a3 += fmaxf(fmaf(fc.y + fd.y, sc.w, sh.w), 0.f); \
    } while (0)
    ADDROW(node);
    int p = g_rowptr[node], end = g_rowptr[node + 1];
    for (; p + 1 < end; p += 2) {
        int j0 = g_adj[p], j1 = g_adj[p + 1];
        ADDROW(j0);
        ADDROW(j1);
    }
    if (p < end) ADDROW(g_adj[p]);
#undef ADDROW
    uint h0, l0, h1, l1;
    split2(a0, a1, h0, l0);
    split2(a2, a3, h1, l1);
    size_t o = (size_t)node * 64 + l * 2;
    *(uint2*)(Oh + o) = make_uint2(h0, h1);
    *(uint2*)(Ol + o) = make_uint2(l0, l1);
}

// ---------------- mma.sync bf16-split3 GEMM (pair inputs): Out = act(A@W + b) ----------------
// 256 threads, 128x128 tile, 8 warps (4m x 2n), warp tile 32x64, k-chunk 16.
template <int K, bool RELU, bool PAIROUT>
__global__ void __launch_bounds__(256, 2)
k_mgemm(const uint* __restrict__ Ah, const uint* __restrict__ Al,
        const uint* __restrict__ Wh, const uint* __restrict__ Wl,
        const float* __restrict__ bias,
        float* __restrict__ OutF, uint* __restrict__ Oh, uint* __restrict__ Ol) {
    __shared__ uint Ash[128][9], Asl[128][9];
    __shared__ uint Bsh[128][9], Bsl[128][9];
    __shared__ float sbias[128];

    const int tid = threadIdx.x;
    const int wid = tid >> 5, lane = tid & 31;
    const int wm = wid >> 1, wn = wid & 1;
    const int g = lane >> 2, t = lane & 3;
    const int row0 = blockIdx.x * 128;
    const int RW = K / 2;

    if (tid < 128) sbias[tid] = bias[tid];

    float acc[2][8][4];
    #pragma unroll
    for (int i = 0; i < 2; i++)
        #pragma unroll
        for (int j = 0; j < 8; j++)
            #pragma unroll
            for (int q = 0; q < 4; q++) acc[i][j][q] = 0.f;

    const int CHK = K / 16;
    for (int c = 0; c < CHK; c++) {
        __syncthreads();
        {   // stage A: pure copies (data already split+packed)
            int r = tid >> 1, half = tid & 1;
            uint4 vh = make_uint4(0, 0, 0, 0), vl = vh;
            if (row0 + r < NN) {
                size_t o = (size_t)(row0 + r) * RW + c * 8 + half * 4;
                vh = *(const uint4*)(Ah + o);
                vl = *(const uint4*)(Al + o);
            }
            int b = half * 4;
            Ash[r][b] = vh.x; Ash[r][b + 1] = vh.y; Ash[r][b + 2] = vh.z; Ash[r][b + 3] = vh.w;
            Asl[r][b] = vl.x; Asl[r][b + 1] = vl.y; Asl[r][b + 2] = vl.z; Asl[r][b + 3] = vl.w;
        }
        {   // stage B: pre-transposed pre-split weights
            int n = tid >> 1, half = tid & 1;
            size_t o = (size_t)n * RW + c * 8 + half * 4;
            uint4 wh = *(const uint4*)(Wh + o);
            uint4 wl = *(const uint4*)(Wl + o);
            int b = half * 4;
            Bsh[n][b] = wh.x; Bsh[n][b + 1] = wh.y; Bsh[n][b + 2] = wh.z; Bsh[n][b + 3] = wh.w;
            Bsl[n][b] = wl.x; Bsl[n][b + 1] = wl.y; Bsl[n][b + 2] = wl.z; Bsl[n][b + 3] = wl.w;
        }
        __syncthreads();
        uint bh[8][2], bl[8][2];
        #pragma unroll
        for (int nt = 0; nt < 8; nt++) {
            int n = wn * 64 + nt * 8 + g;
            bh[nt][0] = Bsh[n][t]; bh[nt][1] = Bsh[n][t + 4];
            bl[nt][0] = Bsl[n][t]; bl[nt][1] = Bsl[n][t + 4];
        }
        #pragma unroll
        for (int mt = 0; mt < 2; mt++) {
            int rb = wm * 32 + mt * 16;
            uint ah0 = Ash[rb + g][t],     ah1 = Ash[rb + 8 + g][t];
            uint ah2 = Ash[rb + g][t + 4], ah3 = Ash[rb + 8 + g][t + 4];
            uint al0 = Asl[rb + g][t],     al1 = Asl[rb + 8 + g][t];
            uint al2 = Asl[rb + g][t + 4], al3 = Asl[rb + 8 + g][t + 4];
            #pragma unroll
            for (int nt = 0; nt < 8; nt++) {
                mma16816(acc[mt][nt], ah0, ah1, ah2, ah3, bh[nt][0], bh[nt][1]);
                mma16816(acc[mt][nt], ah0, ah1, ah2, ah3, bl[nt][0], bl[nt][1]);
                mma16816(acc[mt][nt], al0, al1, al2, al3, bh[nt][0], bh[nt][1]);
            }
        }
    }
    // epilogue
    #pragma unroll
    for (int mt = 0; mt < 2; mt++) {
        #pragma unroll
        for (int nt = 0; nt < 8; nt++) {
            int cc = wn * 64 + nt * 8 + 2 * t;
            float b0 = sbias[cc], b1 = sbias[cc + 1];
            int r0r = row0 + wm * 32 + mt * 16 + g;
            float d0 = acc[mt][nt][0] + b0, d1 = acc[mt][nt][1] + b1;
            float d2 = acc[mt][nt][2] + b0, d3 = acc[mt][nt][3] + b1;
            if (RELU) {
                d0 = fmaxf(d0, 0.f); d1 = fmaxf(d1, 0.f);
                d2 = fmaxf(d2, 0.f); d3 = fmaxf(d3, 0.f);
            }
            if (PAIROUT) {
                uint h, l;
                if (r0r < NN) {
                    split2(d0, d1, h, l);
                    Oh[(size_t)r0r * 64 + (cc >> 1)] = h;
                    Ol[(size_t)r0r * 64 + (cc >> 1)] = l;
                }
                if (r0r + 8 < NN) {
                    split2(d2, d3, h, l);
                    Oh[(size_t)(r0r + 8) * 64 + (cc >> 1)] = h;
                    Ol[(size_t)(r0r + 8) * 64 + (cc >> 1)] = l;
                }
            } else {
                if (r0r < NN) *(float2*)(OutF + (size_t)r0r * 128 + cc) = make_float2(d0, d1);
                if (r0r + 8 < NN) *(float2*)(OutF + (size_t)(r0r + 8) * 128 + cc) = make_float2(d2, d3);
            }
        }
    }
}

// ---------------- BatchNorm ----------------
__global__ void k_zero_stats() { g_stats[threadIdx.x] = 0.f; }

__global__ void k_stats_pair(const uint* __restrict__ Ih, const uint* __restrict__ Il) {
    int c = threadIdx.x;          // 0..127
    int half = c & 1;
    float s = 0.f, q = 0.f;
    for (int r = blockIdx.x; r < NN; r += gridDim.x) {
        size_t o = (size_t)r * 64 + (c >> 1);
        float2 fh = bf2f(Ih[o]);
        float2 fl = bf2f(Il[o]);
        float v = half ? (fh.y + fl.y) : (fh.x + fl.x);
        s += v;
        q = fmaf(v, v, q);
    }
    atomicAdd(&g_stats[c], s);
    atomicAdd(&g_stats[128 + c], q);
}

__global__ void k_bnfin(const float* __restrict__ g, const float* __restrict__ b) {
    int c = threadIdx.x;
    float inv = 1.f / (float)NN;
    float mean = g_stats[c] * inv;
    float var = g_stats[128 + c] * inv - mean * mean;
    float rstd = rsqrtf(var + 1e-5f);
    float sc = g[c] * rstd;
    g_stats[256 + c] = sc;
    g_stats[384 + c] = b[c] - mean * sc;
}

// bnapply2: pair in -> fp32 latent (d_out) + pair out (classifier input)
__global__ void k_bnapply2(const uint* __restrict__ Ih, const uint* __restrict__ Il,
                           float* __restrict__ OutF, uint* __restrict__ Oh,
                           uint* __restrict__ Ol) {
    int i = blockIdx.x * blockDim.x + threadIdx.x;
    if (i >= NN * 64) return;
    int pc = i & 63;
    int c = pc * 2;
    float2 fh = bf2f(Ih[i]);
    float2 fl = bf2f(Il[i]);
    float v0 = fh.x + fl.x, v1 = fh.y + fl.y;
    float y0 = fmaxf(fmaf(v0, g_stats[256 + c], g_stats[384 + c]), 0.f);
    float y1 = fmaxf(fmaf(v1, g_stats[257 + c], g_stats[385 + c]), 0.f);
    int r = i >> 6;
    *(float2*)(OutF + (size_t)r * 128 + c) = make_float2(y0, y1);
    uint h, l;
    split2(y0, y1, h, l);
    Oh[i] = h;
    Ol[i] = l;
}

// ---------------- classifier head: out[N,10] = m[N,128] @ w[128,10] + b ----------------
__global__ void __launch_bounds__(128) k_out(const float* __restrict__ m,
                                             const float* __restrict__ w,
                                             const float* __restrict__ b,
                                             float* __restrict__ out) {
    __shared__ float Wsm[1280];
    __shared__ float Ms[128][33];
    int tid = threadIdx.x;
    for (int i = tid; i < 1280; i += 128) Wsm[i] = w[i];
    long long row0 = (long long)blockIdx.x * 128;
    float acc[10];
    #pragma unroll
    for (int c = 0; c < 10; c++) acc[c] = b[c];
    for (int k0 = 0; k0 < 128; k0 += 32) {
        __syncthreads();
        for (int i = tid; i < 1024; i += 128) {
            int r = i >> 3, c4 = i & 7;
            long long gr = row0 + r;
            float4 v = make_float4(0.f, 0.f, 0.f, 0.f);
            if (gr < NN) v = *(const float4*)(m + gr * 128 + k0 + c4 * 4);
            Ms[r][c4 * 4] = v.x; Ms[r][c4 * 4 + 1] = v.y;
            Ms[r][c4 * 4 + 2] = v.z; Ms[r][c4 * 4 + 3] = v.w;
        }
        __syncthreads();
        #pragma unroll
        for (int kk = 0; kk < 32; kk++) {
            float a = Ms[tid][kk];
            #pragma unroll
            for (int c = 0; c < 10; c++) acc[c] = fmaf(a, Wsm[(k0 + kk) * 10 + c], acc[c]);
        }
    }
    long long gr = row0 + tid;
    if (gr < NN) {
        #pragma unroll
        for (int c = 0; c < 10; c++) out[gr * 10 + c] = acc[c];
    }
}

// ---------------- launch ----------------
extern "C" void kernel_launch(void* const* d_in, const int* in_sizes, int n_in,
                              void* d_out, int out_size) {
    const float* x    = (const float*)d_in[0];
    const int*   ei   = (const int*)d_in[1];
    const float* w1a = (const float*)d_in[2];  const float* b1a = (const float*)d_in[3];
    const float* w1b = (const float*)d_in[4];  const float* b1b = (const float*)d_in[5];
    const float* w2a = (const float*)d_in[6];  const float* b2a = (const float*)d_in[7];
    const float* w2b = (const float*)d_in[8];  const float* b2b = (const float*)d_in[9];
    const float* bn1g = (const float*)d_in[10]; const float* bn1b = (const float*)d_in[11];
    const float* bn2g = (const float*)d_in[12]; const float* bn2b = (const float*)d_in[13];
    const float* mw1 = (const float*)d_in[14]; const float* mb1 = (const float*)d_in[15];
    const float* mw2 = (const float*)d_in[16]; const float* mb2 = (const float*)d_in[17];
    float* out = (float*)d_out;

    uint *P0h, *P0l, *P1h, *P1l, *P2h, *P2l, *Wh, *Wl;
    float* hh;
    cudaGetSymbolAddress((void**)&P0h, g_P0h); cudaGetSymbolAddress((void**)&P0l, g_P0l);
    cudaGetSymbolAddress((void**)&P1h, g_P1h); cudaGetSymbolAddress((void**)&P1l, g_P1l);
    cudaGetSymbolAddress((void**)&P2h, g_P2h); cudaGetSymbolAddress((void**)&P2l, g_P2l);
    cudaGetSymbolAddress((void**)&Wh, g_Wh);   cudaGetSymbolAddress((void**)&Wl, g_Wl);
    cudaGetSymbolAddress((void**)&hh, g_h);

    const int GB = (NN + 127) / 128;  // 782
    const int EB = (EE + 255) / 256;

    // ---- CSR build (parallel 3-phase scan)
    k_detect<<<1, 32>>>(ei);
    k_zero_deg<<<(NN + 255) / 256, 256>>>();
    k_deg<<<EB, 256>>>(ei);
    k_bsum<<<NB, 1024>>>();
    k_bscan<<<1, 128>>>();
    k_scan3<<<NB, 1024>>>();
    k_fill<<<EB, 256>>>(ei);

    // ---- weight pre-split (slot stride 8192)
    k_wsplit<<<(128 * 32 + 255) / 256, 256>>>(w1a, Wh + 0 * 8192, Wl + 0 * 8192, 64);
    k_wsplit<<<(128 * 64 + 255) / 256, 256>>>(w1b, Wh + 1 * 8192, Wl + 1 * 8192, 128);
    k_wsplit<<<(128 * 64 + 255) / 256, 256>>>(w2a, Wh + 2 * 8192, Wl + 2 * 8192, 128);
    k_wsplit<<<(128 * 64 + 255) / 256, 256>>>(w2b, Wh + 3 * 8192, Wl + 3 * 8192, 128);
    k_wsplit<<<(128 * 64 + 255) / 256, 256>>>(mw1, Wh + 4 * 8192, Wl + 4 * 8192, 128);

    // ---- conv1
    k_gather1<<<(NN * 16 + 127) / 128, 128>>>(x, P0h, P0l);
    k_mgemm<64, true, true><<<GB, 256>>>(P0h, P0l, Wh, Wl, b1a, 0, P1h, P1l);
    k_mgemm<128, false, true><<<GB, 256>>>(P1h, P1l, Wh + 8192, Wl + 8192, b1b, 0, P2h, P2l);
    // ---- bn1 stats (apply fused into gather2)
    k_zero_stats<<<1, 512>>>();
    k_stats_pair<<<512, 128>>>(P2h, P2l);
    k_bnfin<<<1, 128>>>(bn1g, bn1b);
    // ---- conv2 (gather applies relu(bn(.)) per term)
    k_gather2<<<(NN + 3) / 4, 128>>>(P2h, P2l, P0h, P0l);
    k_mgemm<128, true, true><<<GB, 256>>>(P0h, P0l, Wh + 2 * 8192, Wl + 2 * 8192, b2a, 0, P1h, P1l);
    k_mgemm<128, false, true><<<GB, 256>>>(P1h, P1l, Wh + 3 * 8192, Wl + 3 * 8192, b2b, 0, P2h, P2l);
    // ---- bn2 -> latent fp32 (d_out) + pair for classifier
    k_zero_stats<<<1, 512>>>();
    k_stats_pair<<<512, 128>>>(P2h, P2l);
    k_bnfin<<<1, 128>>>(bn2g, bn2b);
    k_bnapply2<<<(NN * 64 + 255) / 256, 256>>>(P2h, P2l, out, P0h, P0l);
    // ---- classifier
    k_mgemm<128, true, false><<<GB, 256>>>(P0h, P0l, Wh + 4 * 8192, Wl + 4 * 8192, mb1, hh, 0, 0);
    k_out<<<GB, 128>>>(hh, mw2, mb2, out + (size_t)NN * 128);
}

// round 7
// speedup vs baseline: 1.4746x; 1.2308x over previous
#include <cuda_runtime.h>
#include <cuda_bf16.h>

#define NN 100000
#define FF 64
#define HH 128
#define CC 10
#define EE 1600000
#define NB 98   // ceil(NN/1024)

typedef unsigned int uint;

// ---------------- scratch ----------------
__device__ uint g_P0h[(size_t)NN * 64], g_P0l[(size_t)NN * 64];
__device__ uint g_P1h[(size_t)NN * 64], g_P1l[(size_t)NN * 64];
__device__ uint g_P2h[(size_t)NN * 64], g_P2l[(size_t)NN * 64];
__device__ float g_h[(size_t)NN * HH];
__device__ uint g_Wh[5 * 8192], g_Wl[5 * 8192];
__device__ int g_deg[NN], g_rowptr[NN + 1], g_cur[NN], g_adj[EE];
__device__ int g_bsum[NB], g_bpre[NB];
__device__ float g_stats[512];   // [0:128) sum [128:256) sumsq [256:384) scale [384:512) shift
__device__ int g_is64;

// ---------------- helpers ----------------
__device__ __forceinline__ uint pckbf(__nv_bfloat16 a, __nv_bfloat16 b) {
    __nv_bfloat162 t; t.x = a; t.y = b;
    return *reinterpret_cast<uint*>(&t);
}
__device__ __forceinline__ void split2(float x, float y, uint& h, uint& l) {
    __nv_bfloat16 hx = __float2bfloat16_rn(x), hy = __float2bfloat16_rn(y);
    float rx = x - __bfloat162float(hx), ry = y - __bfloat162float(hy);
    h = pckbf(hx, hy);
    l = pckbf(__float2bfloat16_rn(rx), __float2bfloat16_rn(ry));
}
__device__ __forceinline__ float2 bf2f(uint u) {
    __nv_bfloat162 b = *reinterpret_cast<__nv_bfloat162*>(&u);
    return make_float2(__bfloat162float(b.x), __bfloat162float(b.y));
}
__device__ __forceinline__ void mma16816(float* d, uint a0, uint a1, uint a2,
                                         uint a3, uint b0, uint b1) {
    asm volatile("mma.sync.aligned.m16n8k16.row.col.f32.bf16.bf16.f32 "
                 "{%0,%1,%2,%3},{%4,%5,%6,%7},{%8,%9},{%0,%1,%2,%3};"
                 : "+f"(d[0]), "+f"(d[1]), "+f"(d[2]), "+f"(d[3])
                 : "r"(a0), "r"(a1), "r"(a2), "r"(a3), "r"(b0), "r"(b1));
}
__device__ __forceinline__ void eidx(const int* ei, int e, int& s, int& d) {
    if (g_is64) { s = ei[2 * e]; d = ei[2 * EE + 2 * e]; }
    else        { s = ei[e];     d = ei[EE + e]; }
}
__device__ __forceinline__ uint smem_u32(const void* p) {
    uint a;
    asm("{ .reg .u64 t; cvta.to.shared.u64 t, %1; cvt.u32.u64 %0, t; }" : "=r"(a) : "l"(p));
    return a;
}
__device__ __forceinline__ void cpa16(uint dst, const void* src, int sz) {
    asm volatile("cp.async.cg.shared.global [%0], [%1], 16, %2;"
                 :: "r"(dst), "l"(src), "r"(sz));
}
#define CPA_COMMIT() asm volatile("cp.async.commit_group;" ::: "memory")
#define CPA_WAIT1()  asm volatile("cp.async.wait_group 1;" ::: "memory")
#define CPA_WAIT0()  asm volatile("cp.async.wait_group 0;" ::: "memory")

// ---------------- CSR build ----------------
__global__ void k_init(const int* __restrict__ ei) {
    int i = blockIdx.x * blockDim.x + threadIdx.x;
    if (i < NN) g_deg[i] = 0;
    if (i == 0) {
        int nz = 0;
        for (int k = 0; k < 1024; k++) nz |= ei[2 * k + 1];
        g_is64 = (nz == 0) ? 1 : 0;
    }
}
__global__ void k_deg(const int* __restrict__ ei) {
    int e = blockIdx.x * blockDim.x + threadIdx.x;
    if (e >= EE) return;
    int s, d;
    eidx(ei, e, s, d);
    if ((unsigned)s >= NN || (unsigned)d >= NN) return;
    atomicAdd(&g_deg[d], 1);
}
__global__ void k_bsum() {
    __shared__ int sh[1024];
    int t = threadIdx.x;
    int i = blockIdx.x * 1024 + t;
    sh[t] = (i < NN) ? g_deg[i] : 0;
    __syncthreads();
    for (int off = 512; off > 0; off >>= 1) {
        if (t < off) sh[t] += sh[t + off];
        __syncthreads();
    }
    if (t == 0) g_bsum[blockIdx.x] = sh[0];
}
__global__ void k_bscan() {
    __shared__ int sh[128];
    int t = threadIdx.x;
    sh[t] = (t < NB) ? g_bsum[t] : 0;
    __syncthreads();
    for (int off = 1; off < 128; off <<= 1) {
        int v = (t >= off) ? sh[t - off] : 0;
        __syncthreads();
        sh[t] += v;
        __syncthreads();
    }
    if (t < NB) g_bpre[t] = (t == 0) ? 0 : sh[t - 1];
    if (t == NB - 1) g_rowptr[NN] = sh[t];
}
__global__ void k_scan3() {
    __shared__ int sh[1024];
    int t = threadIdx.x;
    int i = blockIdx.x * 1024 + t;
    int d = (i < NN) ? g_deg[i] : 0;
    sh[t] = d;
    __syncthreads();
    for (int off = 1; off < 1024; off <<= 1) {
        int v = (t >= off) ? sh[t - off] : 0;
        __syncthreads();
        sh[t] += v;
        __syncthreads();
    }
    if (i < NN) {
        int r = g_bpre[blockIdx.x] + sh[t] - d;
        g_rowptr[i] = r;
        g_cur[i] = r;
    }
}
__global__ void k_fill(const int* __restrict__ ei) {
    int e = blockIdx.x * blockDim.x + threadIdx.x;
    if (e >= EE) return;
    int s, d;
    eidx(ei, e, s, d);
    if ((unsigned)s >= NN || (unsigned)d >= NN) return;
    int pos = atomicAdd(&g_cur[d], 1);
    g_adj[pos] = s;
}

// ---------------- weight pre-split (all 5 matrices in one launch) ----------------
__global__ void k_wsplit_all(const float* __restrict__ w1a, const float* __restrict__ w1b,
                             const float* __restrict__ w2a, const float* __restrict__ w2b,
                             const float* __restrict__ mw1) {
    int i = blockIdx.x * blockDim.x + threadIdx.x;
    if (i >= 4096 + 4 * 8192) return;
    const float* W;
    int slot, li, RW;
    if (i < 4096) { W = w1a; slot = 0; li = i; RW = 32; }
    else {
        int j = i - 4096;
        int s = j >> 13;
        li = j & 8191;
        RW = 64;
        slot = 1 + s;
        W = (s == 0) ? w1b : (s == 1) ? w2a : (s == 2) ? w2b : mw1;
    }
    int n = li / RW, kp = li - n * RW;
    split2(W[(size_t)(2 * kp) * 128 + n], W[(size_t)(2 * kp + 1) * 128 + n],
           g_Wh[slot * 8192 + li], g_Wl[slot * 8192 + li]);
}

// ---------------- gather1: agg = x_self + sum x_j, split to pair (width 64) ----------------
__global__ void k_gather1(const float* __restrict__ x, uint* __restrict__ Oh,
                          uint* __restrict__ Ol) {
    int gi = blockIdx.x * blockDim.x + threadIdx.x;
    int node = gi >> 4, l = gi & 15;
    if (node >= NN) return;
    const float4* xr = (const float4*)x;
    float4 acc = xr[(size_t)node * 16 + l];
    int p = g_rowptr[node], end = g_rowptr[node + 1];
    for (; p + 1 < end; p += 2) {
        int j0 = g_adj[p], j1 = g_adj[p + 1];
        float4 a = xr[(size_t)j0 * 16 + l];
        float4 b = xr[(size_t)j1 * 16 + l];
        acc.x += a.x + b.x; acc.y += a.y + b.y;
        acc.z += a.z + b.z; acc.w += a.w + b.w;
    }
    if (p < end) {
        float4 a = xr[(size_t)g_adj[p] * 16 + l];
        acc.x += a.x; acc.y += a.y; acc.z += a.z; acc.w += a.w;
    }
    uint h0, l0, h1, l1;
    split2(acc.x, acc.y, h0, l0);
    split2(acc.z, acc.w, h1, l1);
    size_t o = (size_t)node * 32 + l * 2;
    *(uint2*)(Oh + o) = make_uint2(h0, h1);
    *(uint2*)(Ol + o) = make_uint2(l0, l1);
}

// ---------------- gather2: agg = sum_{self+nbrs} relu(bn(v)), pair width 128 ----------------
__global__ void k_gather2(const uint* __restrict__ Ih, const uint* __restrict__ Il,
                          uint* __restrict__ Oh, uint* __restrict__ Ol) {
    int node = blockIdx.x * 4 + (threadIdx.x >> 5);
    int l = threadIdx.x & 31;
    if (node >= NN) return;
    float4 sc = *(const float4*)&g_stats[256 + l * 4];
    float4 sh = *(const float4*)&g_stats[384 + l * 4];
    float a0 = 0.f, a1 = 0.f, a2 = 0.f, a3 = 0.f;
#define ADDROW(j) do { \
        size_t _o = (size_t)(j) * 64 + l * 2; \
        uint2 uh = *(const uint2*)(Ih + _o); \
        uint2 ul = *(const uint2*)(Il + _o); \
        float2 fa = bf2f(uh.x), fb = bf2f(ul.x), fc = bf2f(uh.y), fd = bf2f(ul.y); \
        a0 += fmaxf(fmaf(fa.x + fb.x, sc.x, sh.x), 0.f); \
        a1 += fmaxf(fmaf(fa.y + fb.y, sc.y, sh.y), 0.f); \
        a2 += fmaxf(fmaf(fc.x + fd.x, sc.z, sh.z), 0.f); \
        a3 += fmaxf(fmaf(fc.y + fd.y, sc.w, sh.w), 0.f); \
    } while (0)
    ADDROW(node);
    int p = g_rowptr[node], end = g_rowptr[node + 1];
    for (; p + 1 < end; p += 2) {
        int j0 = g_adj[p], j1 = g_adj[p + 1];
        ADDROW(j0);
        ADDROW(j1);
    }
    if (p < end) ADDROW(g_adj[p]);
#undef ADDROW
    uint h0, l0, h1, l1;
    split2(a0, a1, h0, l0);
    split2(a2, a3, h1, l1);
    size_t o = (size_t)node * 64 + l * 2;
    *(uint2*)(Oh + o) = make_uint2(h0, h1);
    *(uint2*)(Ol + o) = make_uint2(l0, l1);
}

// ---------------- double-buffered cp.async bf16-split3 GEMM ----------------
// OUTMODE: 0 = fp32 out, 1 = pair out, 2 = pair out + BN stats atomics
// smem stage layout (words): Ah @0, Al @1536, Bh @3072, Bl @4608; stage stride 6144.
// Row stride 12 words: 16B-aligned cp.async dsts AND conflict-free fragment reads.
template <int K, bool RELU, int OUTMODE>
__global__ void __launch_bounds__(256, 2)
k_mgemm(const uint* __restrict__ Ah, const uint* __restrict__ Al,
        const uint* __restrict__ Wh, const uint* __restrict__ Wl,
        const float* __restrict__ bias,
        float* __restrict__ OutF, uint* __restrict__ Oh, uint* __restrict__ Ol) {
    extern __shared__ uint smd[];
    __shared__ float sbias[128];

    const int tid = threadIdx.x;
    const int wid = tid >> 5, lane = tid & 31;
    const int wm = wid >> 1, wn = wid & 1;
    const int g = lane >> 2, t = lane & 3;
    const int row0 = blockIdx.x * 128;
    const int RW = K / 2;
    const int CHK = K / 16;

    const int r = tid >> 1, half = tid & 1;
    const uint sb = smem_u32(smd);
    const int rr = min(row0 + r, NN - 1);
    const int okA = (row0 + r < NN) ? 16 : 0;

    if (tid < 128) sbias[tid] = bias[tid];

#define PREFETCH(c, st) do { \
        uint _d = sb + (uint)((st) * 6144 + r * 12 + half * 4) * 4u; \
        size_t _ao = (size_t)rr * RW + (c) * 8 + half * 4; \
        size_t _wo = (size_t)r * RW + (c) * 8 + half * 4; \
        cpa16(_d,         Ah + _ao, okA); \
        cpa16(_d + 6144,  Al + _ao, okA); \
        cpa16(_d + 12288, Wh + _wo, 16); \
        cpa16(_d + 18432, Wl + _wo, 16); \
        CPA_COMMIT(); \
    } while (0)

    float acc[2][8][4];
    #pragma unroll
    for (int i = 0; i < 2; i++)
        #pragma unroll
        for (int j = 0; j < 8; j++)
            #pragma unroll
            for (int q = 0; q < 4; q++) acc[i][j][q] = 0.f;

    PREFETCH(0, 0);

    for (int c = 0; c < CHK; c++) {
        if (c + 1 < CHK) {
            PREFETCH(c + 1, (c + 1) & 1);
            CPA_WAIT1();
        } else {
            CPA_WAIT0();
        }
        __syncthreads();
        const uint* S = smd + (c & 1) * 6144;
        const uint* Sal = S + 1536;
        const uint* Sbh = S + 3072;
        const uint* Sbl = S + 4608;

        uint bh[8][2], bl[8][2];
        #pragma unroll
        for (int nt = 0; nt < 8; nt++) {
            int n = wn * 64 + nt * 8 + g;
            bh[nt][0] = Sbh[n * 12 + t]; bh[nt][1] = Sbh[n * 12 + t + 4];
            bl[nt][0] = Sbl[n * 12 + t]; bl[nt][1] = Sbl[n * 12 + t + 4];
        }
        #pragma unroll
        for (int mt = 0; mt < 2; mt++) {
            int rb = wm * 32 + mt * 16;
            uint ah0 = S[(rb + g) * 12 + t],       ah1 = S[(rb + 8 + g) * 12 + t];
            uint ah2 = S[(rb + g) * 12 + t + 4],   ah3 = S[(rb + 8 + g) * 12 + t + 4];
            uint al0 = Sal[(rb + g) * 12 + t],     al1 = Sal[(rb + 8 + g) * 12 + t];
            uint al2 = Sal[(rb + g) * 12 + t + 4], al3 = Sal[(rb + 8 + g) * 12 + t + 4];
            #pragma unroll
            for (int nt = 0; nt < 8; nt++) {
                mma16816(acc[mt][nt], ah0, ah1, ah2, ah3, bh[nt][0], bh[nt][1]);
                mma16816(acc[mt][nt], ah0, ah1, ah2, ah3, bl[nt][0], bl[nt][1]);
                mma16816(acc[mt][nt], al0, al1, al2, al3, bh[nt][0], bh[nt][1]);
            }
        }
        __syncthreads();
    }
#undef PREFETCH

    // ---- epilogue: bias (+relu), stores, optional fused BN column stats
    #pragma unroll
    for (int nt = 0; nt < 8; nt++) {
        int cc = wn * 64 + nt * 8 + 2 * t;
        float b0 = sbias[cc], b1 = sbias[cc + 1];
        float s0 = 0.f, q0 = 0.f, s1 = 0.f, q1 = 0.f;
        #pragma unroll
        for (int mt = 0; mt < 2; mt++) {
            int r0r = row0 + wm * 32 + mt * 16 + g;
            float d0 = acc[mt][nt][0] + b0, d1 = acc[mt][nt][1] + b1;
            float d2 = acc[mt][nt][2] + b0, d3 = acc[mt][nt][3] + b1;
            if (RELU) {
                d0 = fmaxf(d0, 0.f); d1 = fmaxf(d1, 0.f);
                d2 = fmaxf(d2, 0.f); d3 = fmaxf(d3, 0.f);
            }
            if (OUTMODE >= 1) {
                uint h, l;
                if (r0r < NN) {
                    split2(d0, d1, h, l);
                    Oh[(size_t)r0r * 64 + (cc >> 1)] = h;
                    Ol[(size_t)r0r * 64 + (cc >> 1)] = l;
                }
                if (r0r + 8 < NN) {
                    split2(d2, d3, h, l);
                    Oh[(size_t)(r0r + 8) * 64 + (cc >> 1)] = h;
                    Ol[(size_t)(r0r + 8) * 64 + (cc >> 1)] = l;
                }
            } else {
                if (r0r < NN) *(float2*)(OutF + (size_t)r0r * 128 + cc) = make_float2(d0, d1);
                if (r0r + 8 < NN) *(float2*)(OutF + (size_t)(r0r + 8) * 128 + cc) = make_float2(d2, d3);
            }
            if (OUTMODE == 2) {
                if (r0r < NN) {
                    s0 += d0; q0 = fmaf(d0, d0, q0);
                    s1 += d1; q1 = fmaf(d1, d1, q1);
                }
                if (r0r + 8 < NN) {
                    s0 += d2; q0 = fmaf(d2, d2, q0);
                    s1 += d3; q1 = fmaf(d3, d3, q1);
                }
            }
        }
        if (OUTMODE == 2) {
            #pragma unroll
            for (int off = 4; off < 32; off <<= 1) {
                s0 += __shfl_xor_sync(0xffffffffu, s0, off);
                q0 += __shfl_xor_sync(0xffffffffu, q0, off);
                s1 += __shfl_xor_sync(0xffffffffu, s1, off);
                q1 += __shfl_xor_sync(0xffffffffu, q1, off);
            }
            if (lane < 4) {
                atomicAdd(&g_stats[cc], s0);
                atomicAdd(&g_stats[128 + cc], q0);
                atomicAdd(&g_stats[cc + 1], s1);
                atomicAdd(&g_stats[128 + cc + 1], q1);
            }
        }
    }
}

// ---------------- BN finalize (self-cleans the accumulators for next use) ----------------
__global__ void k_bnfin(const float* __restrict__ g, const float* __restrict__ b) {
    int c = threadIdx.x;
    float inv = 1.f / (float)NN;
    float mean = g_stats[c] * inv;
    float var = g_stats[128 + c] * inv - mean * mean;
    float rstd = rsqrtf(var + 1e-5f);
    float sc = g[c] * rstd;
    g_stats[256 + c] = sc;
    g_stats[384 + c] = b[c] - mean * sc;
    g_stats[c] = 0.f;
    g_stats[128 + c] = 0.f;
}

// bnapply2: pair in -> fp32 latent (d_out) + pair out (classifier input)
__global__ void k_bnapply2(const uint* __restrict__ Ih, const uint* __restrict__ Il,
                           float* __restrict__ OutF, uint* __restrict__ Oh,
                           uint* __restrict__ Ol) {
    int i = blockIdx.x * blockDim.x + threadIdx.x;
    if (i >= NN * 64) return;
    int c = (i & 63) * 2;
    float2 fh = bf2f(Ih[i]);
    float2 fl = bf2f(Il[i]);
    float v0 = fh.x + fl.x, v1 = fh.y + fl.y;
    float y0 = fmaxf(fmaf(v0, g_stats[256 + c], g_stats[384 + c]), 0.f);
    float y1 = fmaxf(fmaf(v1, g_stats[257 + c], g_stats[385 + c]), 0.f);
    int r = i >> 6;
    *(float2*)(OutF + (size_t)r * 128 + c) = make_float2(y0, y1);
    uint h, l;
    split2(y0, y1, h, l);
    Oh[i] = h;
    Ol[i] = l;
}

// ---------------- classifier head: out[N,10] = m[N,128] @ w[128,10] + b ----------------
__global__ void __launch_bounds__(128) k_out(const float* __restrict__ m,
                                             const float* __restrict__ w,
                                             const float* __restrict__ b,
                                             float* __restrict__ out) {
    __shared__ float Wsm[1280];
    __shared__ float Ms[128][33];
    int tid = threadIdx.x;
    for (int i = tid; i < 1280; i += 128) Wsm[i] = w[i];
    long long row0 = (long long)blockIdx.x * 128;
    float acc[10];
    #pragma unroll
    for (int c = 0; c < 10; c++) acc[c] = b[c];
    for (int k0 = 0; k0 < 128; k0 += 32) {
        __syncthreads();
        for (int i = tid; i < 1024; i += 128) {
            int r = i >> 3, c4 = i & 7;
            long long gr = row0 + r;
            float4 v = make_float4(0.f, 0.f, 0.f, 0.f);
            if (gr < NN) v = *(const float4*)(m + gr * 128 + k0 + c4 * 4);
            Ms[r][c4 * 4] = v.x; Ms[r][c4 * 4 + 1] = v.y;
            Ms[r][c4 * 4 + 2] = v.z; Ms[r][c4 * 4 + 3] = v.w;
        }
        __syncthreads();
        #pragma unroll
        for (int kk = 0; kk < 32; kk++) {
            float a = Ms[tid][kk];
            #pragma unroll
            for (int c = 0; c < 10; c++) acc[c] = fmaf(a, Wsm[(k0 + kk) * 10 + c], acc[c]);
        }
    }
    long long gr = row0 + tid;
    if (gr < NN) {
        #pragma unroll
        for (int c = 0; c < 10; c++) out[gr * 10 + c] = acc[c];
    }
}

// ---------------- launch ----------------
extern "C" void kernel_launch(void* const* d_in, const int* in_sizes, int n_in,
                              void* d_out, int out_size) {
    const float* x    = (const float*)d_in[0];
    const int*   ei   = (const int*)d_in[1];
    const float* w1a = (const float*)d_in[2];  const float* b1a = (const float*)d_in[3];
    const float* w1b = (const float*)d_in[4];  const float* b1b = (const float*)d_in[5];
    const float* w2a = (const float*)d_in[6];  const float* b2a = (const float*)d_in[7];
    const float* w2b = (const float*)d_in[8];  const float* b2b = (const float*)d_in[9];
    const float* bn1g = (const float*)d_in[10]; const float* bn1b = (const float*)d_in[11];
    const float* bn2g = (const float*)d_in[12]; const float* bn2b = (const float*)d_in[13];
    const float* mw1 = (const float*)d_in[14]; const float* mb1 = (const float*)d_in[15];
    const float* mw2 = (const float*)d_in[16]; const float* mb2 = (const float*)d_in[17];
    float* out = (float*)d_out;

    uint *P0h, *P0l, *P1h, *P1l, *P2h, *P2l, *Wh, *Wl;
    float* hh;
    cudaGetSymbolAddress((void**)&P0h, g_P0h); cudaGetSymbolAddress((void**)&P0l, g_P0l);
    cudaGetSymbolAddress((void**)&P1h, g_P1h); cudaGetSymbolAddress((void**)&P1l, g_P1l);
    cudaGetSymbolAddress((void**)&P2h, g_P2h); cudaGetSymbolAddress((void**)&P2l, g_P2l);
    cudaGetSymbolAddress((void**)&Wh, g_Wh);   cudaGetSymbolAddress((void**)&Wl, g_Wl);
    cudaGetSymbolAddress((void**)&hh, g_h);

    const int GB = (NN + 127) / 128;  // 782
    const int EB = (EE + 255) / 256;
    const int SMEM_G = 2 * 6144 * 4;  // 49152 B dynamic

    cudaFuncSetAttribute(k_mgemm<64, true, 1>,   cudaFuncAttributeMaxDynamicSharedMemorySize, SMEM_G);
    cudaFuncSetAttribute(k_mgemm<128, false, 2>, cudaFuncAttributeMaxDynamicSharedMemorySize, SMEM_G);
    cudaFuncSetAttribute(k_mgemm<128, true, 1>,  cudaFuncAttributeMaxDynamicSharedMemorySize, SMEM_G);
    cudaFuncSetAttribute(k_mgemm<128, true, 0>,  cudaFuncAttributeMaxDynamicSharedMemorySize, SMEM_G);

    // ---- CSR build
    k_init<<<(NN + 255) / 256, 256>>>(ei);
    k_deg<<<EB, 256>>>(ei);
    k_bsum<<<NB, 1024>>>();
    k_bscan<<<1, 128>>>();
    k_scan3<<<NB, 1024>>>();
    k_fill<<<EB, 256>>>(ei);
    // ---- weight pre-split (one launch)
    k_wsplit_all<<<(4096 + 4 * 8192 + 255) / 256, 256>>>(w1a, w1b, w2a, w2b, mw1);

    // ---- conv1
    k_gather1<<<(NN * 16 + 127) / 128, 128>>>(x, P0h, P0l);
    k_mgemm<64, true, 1><<<GB, 256, SMEM_G>>>(P0h, P0l, Wh, Wl, b1a, 0, P1h, P1l);
    k_mgemm<128, false, 2><<<GB, 256, SMEM_G>>>(P1h, P1l, Wh + 8192, Wl + 8192, b1b, 0, P2h, P2l);
    k_bnfin<<<1, 128>>>(bn1g, bn1b);
    // ---- conv2 (gather applies relu(bn(.)) per term)
    k_gather2<<<(NN + 3) / 4, 128>>>(P2h, P2l, P0h, P0l);
    k_mgemm<128, true, 1><<<GB, 256, SMEM_G>>>(P0h, P0l, Wh + 2 * 8192, Wl + 2 * 8192, b2a, 0, P1h, P1l);
    k_mgemm<128, false, 2><<<GB, 256, SMEM_G>>>(P1h, P1l, Wh + 3 * 8192, Wl + 3 * 8192, b2b, 0, P2h, P2l);
    k_bnfin<<<1, 128>>>(bn2g, bn2b);
    k_bnapply2<<<(NN * 64 + 255) / 256, 256>>>(P2h, P2l, out, P0h, P0l);
    // ---- classifier
    k_mgemm<128, true, 0><<<GB, 256, SMEM_G>>>(P0h, P0l, Wh + 4 * 8192, Wl + 4 * 8192, mb1, hh, 0, 0);
    k_out<<<GB, 128>>>(hh, mw2, mb2, out + (size_t)NN * 128);
}